// round 1
// baseline (speedup 1.0000x reference)
#include <cuda_runtime.h>
#include <cstdint>

// Kohonen SOM pairwise distance: out[b][n] = || x[b] - w[n] ||_2
// via   sq = ||x||^2 + ||w||^2 - 2 x.w   (clamped at 0), then sqrt.
//
// Shapes: x [B=65536, D=32] f32, w [N=4900, D=32] f32, out [B, N] f32.
// Structure: K=32 GEMM, 128x128 block tile, 256 threads, 8x8 per-thread
// micro-tile, accumulation in packed f32x2 (fma.rn.f32x2 -> FFMA2, 2x fp32
// throughput vs scalar FFMA on sm_103a; ptxas never emits it from C++).

#define TILE   128
#define DEPTH  32
#define LDS_PITCH (TILE + 4)   // 132 floats: keeps 16B alignment, breaks store conflicts

__device__ __forceinline__ unsigned long long pack2(float a) {
    unsigned long long r;
    asm("mov.b64 %0, {%1, %1};" : "=l"(r) : "r"(__float_as_uint(a)));
    return r;
}

__device__ __forceinline__ void fma2(unsigned long long &d,
                                     unsigned long long a,
                                     unsigned long long b) {
    // packed f32x2 fused multiply-add: d.lo += a.lo*b.lo ; d.hi += a.hi*b.hi
    asm("fma.rn.f32x2 %0, %1, %2, %0;" : "+l"(d) : "l"(a), "l"(b));
}

__device__ __forceinline__ float fsqrt_approx(float a) {
    float r;
    asm("sqrt.approx.f32 %0, %1;" : "=f"(r) : "f"(a));
    return r;
}

__global__ __launch_bounds__(256, 2)
void som_dist_kernel(const float* __restrict__ x,
                     const float* __restrict__ w,
                     float* __restrict__ out,
                     int B, int N) {
    __shared__ float xs[DEPTH][LDS_PITCH];   // k-major x tile
    __shared__ float ws[DEPTH][LDS_PITCH];   // k-major w tile
    __shared__ float x2s[TILE];
    __shared__ float w2s[TILE];

    const int tid    = threadIdx.x;
    const int m_base = blockIdx.y * TILE;
    const int n_base = blockIdx.x * TILE;

    // ---- load both tiles (transpose to k-major in smem) ----
    // 128 rows x 32 floats = 1024 float4s; 256 threads x 4 passes.
    #pragma unroll
    for (int p = 0; p < 4; ++p) {
        int idx = tid + p * 256;        // float4 index
        int row = idx >> 3;             // 8 float4 per row
        int kq  = (idx & 7) << 2;

        int gm = m_base + row;
        float4 v = (gm < B) ? *(const float4*)(x + (size_t)gm * DEPTH + kq)
                            : make_float4(0.f, 0.f, 0.f, 0.f);
        xs[kq + 0][row] = v.x; xs[kq + 1][row] = v.y;
        xs[kq + 2][row] = v.z; xs[kq + 3][row] = v.w;

        int gn = n_base + row;
        float4 u = (gn < N) ? *(const float4*)(w + (size_t)gn * DEPTH + kq)
                            : make_float4(0.f, 0.f, 0.f, 0.f);
        ws[kq + 0][row] = u.x; ws[kq + 1][row] = u.y;
        ws[kq + 2][row] = u.z; ws[kq + 3][row] = u.w;
    }
    __syncthreads();

    // ---- per-tile norms (conflict-free: consecutive lanes, consecutive banks) ----
    if (tid < TILE) {
        float s = 0.f;
        #pragma unroll
        for (int k = 0; k < DEPTH; ++k) { float v = ws[k][tid]; s = fmaf(v, v, s); }
        w2s[tid] = s;
    } else {
        int m = tid - TILE;
        float s = 0.f;
        #pragma unroll
        for (int k = 0; k < DEPTH; ++k) { float v = xs[k][m]; s = fmaf(v, v, s); }
        x2s[m] = s;
    }
    __syncthreads();

    // ---- 8x8 register micro-tile, packed f32x2 accumulators ----
    const int tx = tid & 15;        // n direction
    const int ty = tid >> 4;        // m direction
    const int tm = ty << 3;
    const int tn = tx << 3;

    unsigned long long acc[8][4];
    #pragma unroll
    for (int i = 0; i < 8; ++i)
        #pragma unroll
        for (int j = 0; j < 4; ++j) acc[i][j] = 0ull;

    #pragma unroll
    for (int k = 0; k < DEPTH; ++k) {
        // w operand: 8 consecutive floats -> 4 natural f32x2 pairs (no pack needed)
        const ulonglong2* wp = (const ulonglong2*)&ws[k][tn];
        ulonglong2 b01 = wp[0];
        ulonglong2 b23 = wp[1];
        unsigned long long b[4] = { b01.x, b01.y, b23.x, b23.y };

        // x operand: 8 scalars, broadcast-packed (alu-pipe MOVs, hidden behind fma pipe)
        float4 a0 = *(const float4*)&xs[k][tm];
        float4 a1 = *(const float4*)&xs[k][tm + 4];
        unsigned long long ap[8] = {
            pack2(a0.x), pack2(a0.y), pack2(a0.z), pack2(a0.w),
            pack2(a1.x), pack2(a1.y), pack2(a1.z), pack2(a1.w)
        };

        #pragma unroll
        for (int i = 0; i < 8; ++i) {
            #pragma unroll
            for (int j = 0; j < 4; ++j) fma2(acc[i][j], ap[i], b[j]);
        }
    }

    // ---- epilogue: sq = x2 + w2 - 2*dot, clamp, sqrt, store ----
    float xn[8], wn[8];
    #pragma unroll
    for (int i = 0; i < 8; ++i) xn[i] = x2s[tm + i];
    #pragma unroll
    for (int j = 0; j < 8; ++j) wn[j] = w2s[tn + j];

    const bool full_n = (n_base + TILE <= N);

    #pragma unroll
    for (int i = 0; i < 8; ++i) {
        int gm = m_base + tm + i;
        if (gm >= B) continue;

        float r[8];
        #pragma unroll
        for (int j = 0; j < 4; ++j) {
            unsigned long long v = acc[i][j];
            float lo = __uint_as_float((unsigned)(v & 0xffffffffull));
            float hi = __uint_as_float((unsigned)(v >> 32));
            float s0 = fmaxf(fmaf(-2.f, lo, xn[i] + wn[2 * j]),     0.f);
            float s1 = fmaxf(fmaf(-2.f, hi, xn[i] + wn[2 * j + 1]), 0.f);
            r[2 * j]     = fsqrt_approx(s0);
            r[2 * j + 1] = fsqrt_approx(s1);
        }

        size_t off = (size_t)gm * N + (size_t)(n_base + tn);
        if (full_n) {
            // N = 4900 is a multiple of 4, tn multiple of 8 -> 16B aligned
            *(float4*)(out + off)     = make_float4(r[0], r[1], r[2], r[3]);
            *(float4*)(out + off + 4) = make_float4(r[4], r[5], r[6], r[7]);
        } else {
            #pragma unroll
            for (int j = 0; j < 8; ++j) {
                int gn = n_base + tn + j;
                if (gn < N) out[off + j] = r[j];
            }
        }
    }
}

extern "C" void kernel_launch(void* const* d_in, const int* in_sizes, int n_in,
                              void* d_out, int out_size) {
    const float* x = (const float*)d_in[0];
    const float* w = (const float*)d_in[1];
    float* out     = (float*)d_out;

    int B = in_sizes[0] / DEPTH;   // 65536
    int N = in_sizes[1] / DEPTH;   // 4900

    dim3 grid((N + TILE - 1) / TILE, (B + TILE - 1) / TILE);
    som_dist_kernel<<<grid, 256>>>(x, w, out, B, N);
}

// round 3
// speedup vs baseline: 1.1822x; 1.1822x over previous
#include <cuda_runtime.h>
#include <cstdint>

// Kohonen SOM pairwise L2 distance via portable tf32 tensor-core MMA
// (mma.sync.m16n8k8 — baseline PTX, compiles for compute_103; tcgen05 is
// rejected by this harness's virtual-arch target).
//
//   out[b][n] = sqrt(max(||x_b||^2 + ||w_n||^2 - 2 x_b.w_n, 0))
// x [B=65536,32] f32, w [N=4900,32] f32, out [B,N] f32.
//
// Block: 128x128 tile, 256 threads (8 warps, 4x2 warp grid, 32x64 per warp).
// K=32 fully resident in smem; 4 unrolled k-steps of m16n8k8 tf32 MMAs.
// Norms computed in fp32 during the smem fill; operands tf32-rounded once.

#define BM 128
#define BN 128
#define KD 32
#define SPITCH 36   // floats; (row*36 + col) % 32 == (4*row + col) % 32 -> all
                    // m16n8k8 fragment reads hit 32 distinct banks

__device__ __forceinline__ float to_tf32(float a) {
    float r;
    asm("cvt.rna.tf32.f32 %0, %1;" : "=f"(r) : "f"(a));
    return r;
}

__device__ __forceinline__ float fsqrt_approx(float a) {
    float r;
    asm("sqrt.approx.f32 %0, %1;" : "=f"(r) : "f"(a));
    return r;
}

__device__ __forceinline__ void mma_tf32(float* c, const unsigned* a, const unsigned* b) {
    asm volatile(
        "mma.sync.aligned.m16n8k8.row.col.f32.tf32.tf32.f32 "
        "{%0,%1,%2,%3}, {%4,%5,%6,%7}, {%8,%9}, {%0,%1,%2,%3};"
        : "+f"(c[0]), "+f"(c[1]), "+f"(c[2]), "+f"(c[3])
        : "r"(a[0]), "r"(a[1]), "r"(a[2]), "r"(a[3]),
          "r"(b[0]), "r"(b[1]));
}

__global__ __launch_bounds__(256, 2)
void som_mma_kernel(const float* __restrict__ x,
                    const float* __restrict__ w,
                    float* __restrict__ out,
                    int B, int N) {
    __shared__ float As[BM][SPITCH];
    __shared__ float Bs[BN][SPITCH];
    __shared__ float x2s[BM];
    __shared__ float w2s[BN];

    const int tid    = threadIdx.x;
    const int m_base = blockIdx.y * BM;
    const int n_base = blockIdx.x * BN;

    // ---- fill smem: one row per thread; norm in fp32, operand tf32-rounded ----
    if (tid < BM) {
        const float4* src = (const float4*)(x + (size_t)(m_base + tid) * KD);
        float nrm = 0.f;
        #pragma unroll
        for (int q = 0; q < 8; ++q) {
            float4 v = src[q];
            nrm = fmaf(v.x, v.x, nrm); nrm = fmaf(v.y, v.y, nrm);
            nrm = fmaf(v.z, v.z, nrm); nrm = fmaf(v.w, v.w, nrm);
            float4 t = make_float4(to_tf32(v.x), to_tf32(v.y),
                                   to_tf32(v.z), to_tf32(v.w));
            *(float4*)&As[tid][q * 4] = t;          // 16B-aligned: 36*4 and q*16
        }
        x2s[tid] = nrm;
    } else {
        const int row = tid - BM;
        const int gn  = n_base + row;
        float nrm = 0.f;
        if (gn < N) {
            const float4* src = (const float4*)(w + (size_t)gn * KD);
            #pragma unroll
            for (int q = 0; q < 8; ++q) {
                float4 v = src[q];
                nrm = fmaf(v.x, v.x, nrm); nrm = fmaf(v.y, v.y, nrm);
                nrm = fmaf(v.z, v.z, nrm); nrm = fmaf(v.w, v.w, nrm);
                float4 t = make_float4(to_tf32(v.x), to_tf32(v.y),
                                       to_tf32(v.z), to_tf32(v.w));
                *(float4*)&Bs[row][q * 4] = t;
            }
        } else {
            float4 z = make_float4(0.f, 0.f, 0.f, 0.f);
            #pragma unroll
            for (int q = 0; q < 8; ++q) *(float4*)&Bs[row][q * 4] = z;
        }
        w2s[row] = nrm;
    }
    __syncthreads();

    // ---- warp-tiled tf32 MMA mainloop ----
    const int lane   = tid & 31;
    const int wid    = tid >> 5;
    const int warp_m = (wid & 3) * 32;   // 4 warps along M
    const int warp_n = (wid >> 2) * 64;  // 2 warps along N
    const int qr     = lane >> 2;        // 0..7
    const int qc     = lane & 3;         // 0..3

    float acc[2][8][4];
    #pragma unroll
    for (int i = 0; i < 2; ++i)
        #pragma unroll
        for (int j = 0; j < 8; ++j)
            #pragma unroll
            for (int v = 0; v < 4; ++v) acc[i][j][v] = 0.f;

    #pragma unroll
    for (int ks = 0; ks < 4; ++ks) {
        const int k0 = ks * 8;

        unsigned af[2][4];
        #pragma unroll
        for (int tm = 0; tm < 2; ++tm) {
            const int r = warp_m + tm * 16 + qr;
            af[tm][0] = __float_as_uint(As[r    ][k0 + qc    ]);
            af[tm][1] = __float_as_uint(As[r + 8][k0 + qc    ]);
            af[tm][2] = __float_as_uint(As[r    ][k0 + qc + 4]);
            af[tm][3] = __float_as_uint(As[r + 8][k0 + qc + 4]);
        }

        unsigned bf[8][2];
        #pragma unroll
        for (int tn = 0; tn < 8; ++tn) {
            const int c = warp_n + tn * 8 + qr;
            bf[tn][0] = __float_as_uint(Bs[c][k0 + qc    ]);
            bf[tn][1] = __float_as_uint(Bs[c][k0 + qc + 4]);
        }

        #pragma unroll
        for (int tm = 0; tm < 2; ++tm)
            #pragma unroll
            for (int tn = 0; tn < 8; ++tn)
                mma_tf32(acc[tm][tn], af[tm], bf[tn]);
    }

    // ---- epilogue: norms + sqrt, float2 stores (8B-aligned: N even, col even) ----
    const int qc2 = qc * 2;
    #pragma unroll
    for (int tm = 0; tm < 2; ++tm) {
        const int r_lo = warp_m + tm * 16 + qr;
        const float x2_lo = x2s[r_lo];
        const float x2_hi = x2s[r_lo + 8];
        const size_t off_lo = (size_t)(m_base + r_lo) * N;
        const size_t off_hi = off_lo + (size_t)8 * N;

        #pragma unroll
        for (int tn = 0; tn < 8; ++tn) {
            const int c  = warp_n + tn * 8 + qc2;
            const int gn = n_base + c;
            if (gn < N) {                     // N even, c even -> gn+1 < N too
                const float w2a = w2s[c];
                const float w2b = w2s[c + 1];
                const float* a = acc[tm][tn];

                float2 lo, hi;
                lo.x = fsqrt_approx(fmaxf(fmaf(-2.f, a[0], x2_lo + w2a), 0.f));
                lo.y = fsqrt_approx(fmaxf(fmaf(-2.f, a[1], x2_lo + w2b), 0.f));
                hi.x = fsqrt_approx(fmaxf(fmaf(-2.f, a[2], x2_hi + w2a), 0.f));
                hi.y = fsqrt_approx(fmaxf(fmaf(-2.f, a[3], x2_hi + w2b), 0.f));

                *(float2*)(out + off_lo + gn) = lo;
                *(float2*)(out + off_hi + gn) = hi;
            }
        }
    }
}

extern "C" void kernel_launch(void* const* d_in, const int* in_sizes, int n_in,
                              void* d_out, int out_size) {
    const float* x = (const float*)d_in[0];
    const float* w = (const float*)d_in[1];
    float* out     = (float*)d_out;

    int B = in_sizes[0] / KD;   // 65536
    int N = in_sizes[1] / KD;   // 4900

    dim3 grid((N + BN - 1) / BN, (B + BM - 1) / BM);
    som_mma_kernel<<<grid, 256>>>(x, w, out, B, N);
}

// round 4
// speedup vs baseline: 1.2038x; 1.0182x over previous
#include <cuda_runtime.h>
#include <cstdint>

// Kohonen SOM pairwise L2 distance via tf32 mma.sync.m16n8k8.
//   out[b][n] = sqrt(max(||x_b||^2 + ||w_n||^2 - 2 x_b.w_n, 0))
// x [B=65536,32] f32, w [N=4900,32] f32, out [B,N] f32.
//
// 128x128 block tile, 256 threads (4x2 warp grid, 32x64 per warp), K=32
// resident in smem. Epilogue is smem-STAGED: final values are written to a
// reused smem buffer and copied out row-contiguously (STG.128, 512 B per
// warp-instruction) instead of the fragment-order STG.64 pattern that cost
// 8 quarter-filled wavefronts per instruction.

#define BM 128
#define BN 128
#define KD 32
#define SPITCH 36    // operand tiles: (4*row + col) % 32 distinct -> conflict-free
#define OPITCH 132   // stage buffer pitch (floats); row base stays 16B-aligned

// smem: As/Bs operand tiles overlaid with the 64x132 stage buffer.
#define SM_FLOATS (2 * BM * SPITCH)          // 9216 floats = 36864 B (stage needs 8448)
__shared__ float sm_buf[SM_FLOATS];
__shared__ float x2s[BM];
__shared__ float w2s[BN];

__device__ __forceinline__ float to_tf32(float a) {
    float r;
    asm("cvt.rna.tf32.f32 %0, %1;" : "=f"(r) : "f"(a));
    return r;
}

__device__ __forceinline__ float fsqrt_approx(float a) {
    float r;
    asm("sqrt.approx.f32 %0, %1;" : "=f"(r) : "f"(a));
    return r;
}

__device__ __forceinline__ void mma_tf32(float* c, const unsigned* a, const unsigned* b) {
    asm volatile(
        "mma.sync.aligned.m16n8k8.row.col.f32.tf32.tf32.f32 "
        "{%0,%1,%2,%3}, {%4,%5,%6,%7}, {%8,%9}, {%0,%1,%2,%3};"
        : "+f"(c[0]), "+f"(c[1]), "+f"(c[2]), "+f"(c[3])
        : "r"(a[0]), "r"(a[1]), "r"(a[2]), "r"(a[3]),
          "r"(b[0]), "r"(b[1]));
}

__global__ __launch_bounds__(256, 2)
void som_mma_kernel(const float* __restrict__ x,
                    const float* __restrict__ w,
                    float* __restrict__ out,
                    int B, int N) {
    float* As = sm_buf;                 // [BM][SPITCH]
    float* Bs = sm_buf + BM * SPITCH;   // [BN][SPITCH]

    const int tid    = threadIdx.x;
    const int m_base = blockIdx.y * BM;
    const int n_base = blockIdx.x * BN;

    // ---- fill operand tiles; norms in fp32, operands tf32-rounded ----
    if (tid < BM) {
        const float4* src = (const float4*)(x + (size_t)(m_base + tid) * KD);
        float nrm = 0.f;
        #pragma unroll
        for (int q = 0; q < 8; ++q) {
            float4 v = src[q];
            nrm = fmaf(v.x, v.x, nrm); nrm = fmaf(v.y, v.y, nrm);
            nrm = fmaf(v.z, v.z, nrm); nrm = fmaf(v.w, v.w, nrm);
            float4 t = make_float4(to_tf32(v.x), to_tf32(v.y),
                                   to_tf32(v.z), to_tf32(v.w));
            *(float4*)&As[tid * SPITCH + q * 4] = t;
        }
        x2s[tid] = nrm;
    } else {
        const int row = tid - BM;
        const int gn  = n_base + row;
        float nrm = 0.f;
        if (gn < N) {
            const float4* src = (const float4*)(w + (size_t)gn * KD);
            #pragma unroll
            for (int q = 0; q < 8; ++q) {
                float4 v = src[q];
                nrm = fmaf(v.x, v.x, nrm); nrm = fmaf(v.y, v.y, nrm);
                nrm = fmaf(v.z, v.z, nrm); nrm = fmaf(v.w, v.w, nrm);
                float4 t = make_float4(to_tf32(v.x), to_tf32(v.y),
                                       to_tf32(v.z), to_tf32(v.w));
                *(float4*)&Bs[row * SPITCH + q * 4] = t;
            }
        } else {
            float4 z = make_float4(0.f, 0.f, 0.f, 0.f);
            #pragma unroll
            for (int q = 0; q < 8; ++q) *(float4*)&Bs[row * SPITCH + q * 4] = z;
        }
        w2s[row] = nrm;
    }
    __syncthreads();

    // ---- warp-tiled tf32 MMA mainloop ----
    const int lane   = tid & 31;
    const int wid    = tid >> 5;
    const int mw     = wid & 3;          // 4 warps along M
    const int warp_m = mw * 32;
    const int warp_n = (wid >> 2) * 64;  // 2 warps along N
    const int qr     = lane >> 2;        // 0..7
    const int qc     = lane & 3;         // 0..3

    float acc[2][8][4];
    #pragma unroll
    for (int i = 0; i < 2; ++i)
        #pragma unroll
        for (int j = 0; j < 8; ++j)
            #pragma unroll
            for (int v = 0; v < 4; ++v) acc[i][j][v] = 0.f;

    #pragma unroll
    for (int ks = 0; ks < 4; ++ks) {
        const int k0 = ks * 8;

        unsigned af[2][4];
        #pragma unroll
        for (int tm = 0; tm < 2; ++tm) {
            const int r = warp_m + tm * 16 + qr;
            af[tm][0] = __float_as_uint(As[(r    ) * SPITCH + k0 + qc    ]);
            af[tm][1] = __float_as_uint(As[(r + 8) * SPITCH + k0 + qc    ]);
            af[tm][2] = __float_as_uint(As[(r    ) * SPITCH + k0 + qc + 4]);
            af[tm][3] = __float_as_uint(As[(r + 8) * SPITCH + k0 + qc + 4]);
        }

        unsigned bf[8][2];
        #pragma unroll
        for (int tn = 0; tn < 8; ++tn) {
            const int c = warp_n + tn * 8 + qr;
            bf[tn][0] = __float_as_uint(Bs[c * SPITCH + k0 + qc    ]);
            bf[tn][1] = __float_as_uint(Bs[c * SPITCH + k0 + qc + 4]);
        }

        #pragma unroll
        for (int tm = 0; tm < 2; ++tm)
            #pragma unroll
            for (int tn = 0; tn < 8; ++tn)
                mma_tf32(acc[tm][tn], af[tm], bf[tn]);
    }

    // ---- staged epilogue: two 64-row passes through smem ----
    float* stage = sm_buf;               // [64][OPITCH], aliases As/Bs (dead now)
    const int nb_valid = N - n_base;     // columns valid in this tile (B%BM==0)

    #pragma unroll
    for (int tm = 0; tm < 2; ++tm) {
        __syncthreads();   // pass 0->1: prior reads done; pass 0: mainloop LDS done

        // write: finals for rows (stage rows s0 = mw*16+qr, s1 = s0+8)
        {
            const int lr0 = warp_m + tm * 16 + qr;       // local rows in tile
            const float x2_lo = x2s[lr0];
            const float x2_hi = x2s[lr0 + 8];
            const int s0 = mw * 16 + qr;
            const int qc2 = qc * 2;

            #pragma unroll
            for (int tn = 0; tn < 8; ++tn) {
                const int c   = warp_n + tn * 8 + qc2;
                const float w2a = w2s[c];
                const float w2b = w2s[c + 1];
                const float* a  = acc[tm][tn];

                float2 lo, hi;
                lo.x = fsqrt_approx(fmaxf(fmaf(-2.f, a[0], x2_lo + w2a), 0.f));
                lo.y = fsqrt_approx(fmaxf(fmaf(-2.f, a[1], x2_lo + w2b), 0.f));
                hi.x = fsqrt_approx(fmaxf(fmaf(-2.f, a[2], x2_hi + w2a), 0.f));
                hi.y = fsqrt_approx(fmaxf(fmaf(-2.f, a[3], x2_hi + w2b), 0.f));

                *(float2*)&stage[(s0    ) * OPITCH + c] = lo;
                *(float2*)&stage[(s0 + 8) * OPITCH + c] = hi;
            }
        }
        __syncthreads();

        // read: warp copies full rows; 32 lanes x float4 = 512 B contiguous
        #pragma unroll
        for (int it = 0; it < 8; ++it) {
            const int s  = it * 8 + wid;                       // 0..63
            const int lr = (s >> 4) * 32 + tm * 16 + (s & 15); // local row
            const size_t row_off = (size_t)(m_base + lr) * N + n_base;
            const int c4 = lane * 4;

            float4 v = *(const float4*)&stage[s * OPITCH + c4];
            if (c4 + 4 <= nb_valid) {
                __stcs((float4*)(out + row_off + c4), v);
            } else if (c4 < nb_valid) {
                float t[4] = {v.x, v.y, v.z, v.w};
                for (int j = 0; j < nb_valid - c4; ++j)
                    __stcs(out + row_off + c4 + j, t[j]);
            }
        }
    }
}

extern "C" void kernel_launch(void* const* d_in, const int* in_sizes, int n_in,
                              void* d_out, int out_size) {
    const float* x = (const float*)d_in[0];
    const float* w = (const float*)d_in[1];
    float* out     = (float*)d_out;

    int B = in_sizes[0] / KD;   // 65536
    int N = in_sizes[1] / KD;   // 4900

    dim3 grid((N + BN - 1) / BN, (B + BM - 1) / BM);
    som_mma_kernel<<<grid, 256>>>(x, w, out, B, N);
}